// round 1
// baseline (speedup 1.0000x reference)
#include <cuda_runtime.h>

// KAN_Convolution: 2x2 unfold over (8,16,128,128), KANLinear(4->1) per patch,
// sum over 16 channels -> (8,1,127,127) fp32.
//
// Strategy:
//  - Uniform knot grid => closed-form piecewise-cubic B-spline. Per block we
//    precompute an 11x4x4 Horner coefficient table from the scaled spline
//    weights (zero-padded outside j in [0,8)).
//  - Each input element's 4 per-position contributions d_k(v) are computed ONCE
//    (1 exp + 1 rcp + 4 cubic Horners) and staged in shared memory; each output
//    thread gathers its 4 contributions. This cuts SiLU/spline evals ~3.5x vs
//    per-output evaluation (MUFU was the predicted bottleneck).
//
// Tile: 32(w) x 8(h) outputs per 256-thread block; halo input tile 33x9.

#define TW 32
#define TH 8
#define HALO_W 33
#define HALO_H 9
#define NELEM (HALO_W * HALO_H)   // 297
#define PLANE 304                 // padded

__global__ __launch_bounds__(256)
void kan_conv_kernel(const float* __restrict__ x,
                     const float* __restrict__ base_w,
                     const float* __restrict__ spline_w,
                     const float* __restrict__ spline_sc,
                     const float* __restrict__ grid,
                     float* __restrict__ out)
{
    __shared__ float  sh_wpad[4 * 14];       // padded scaled weights, j in [-3, 10]
    __shared__ float4 sh_coef4[11 * 4];      // [interval][k] -> (c0,c1,c2,c3)
    __shared__ float  sh_d[4][PLANE];        // per-k contribution planes

    const int tid = threadIdx.x;

    // ---- build padded scaled spline weights ----
    if (tid < 56) {
        int k = tid / 14, jj = tid % 14, j = jj - 3;
        float v = 0.0f;
        if (j >= 0 && j < 8) v = spline_w[k * 8 + j] * spline_sc[k];
        sh_wpad[k * 14 + jj] = v;
    }
    __syncthreads();

    // ---- build per-interval cubic coefficients (Horner in u) ----
    // On interval i with u in [0,1): active bases j=i-3..i:
    //   B_{i-3}=(1-u)^3/6, B_{i-2}=(3u^3-6u^2+4)/6,
    //   B_{i-1}=(-3u^3+3u^2+3u+1)/6, B_i=u^3/6
    if (tid < 176) {
        int i = tid >> 4, rem = tid & 15, k = rem >> 2, m = rem & 3;
        float wA = sh_wpad[k * 14 + i];
        float wB = sh_wpad[k * 14 + i + 1];
        float wC = sh_wpad[k * 14 + i + 2];
        float wD = sh_wpad[k * 14 + i + 3];
        float cv;
        if (m == 0)      cv = (wA + 4.0f * wB + wC) * (1.0f / 6.0f);
        else if (m == 1) cv = 0.5f * (wC - wA);
        else if (m == 2) cv = 0.5f * (wA - 2.0f * wB + wC);
        else             cv = (wD - wA + 3.0f * (wB - wC)) * (1.0f / 6.0f);
        ((float*)sh_coef4)[(i * 4 + k) * 4 + m] = cv;
    }

    const float g0   = __ldg(grid);
    const float g1   = __ldg(grid + 1);
    const float g11  = __ldg(grid + 11);
    const float invh = 1.0f / (g1 - g0);
    const float bw0 = __ldg(base_w + 0);
    const float bw1 = __ldg(base_w + 1);
    const float bw2 = __ldg(base_w + 2);
    const float bw3 = __ldg(base_w + 3);
    __syncthreads();

    const int w0 = blockIdx.x * TW;
    const int h0 = blockIdx.y * TH;
    const int b  = blockIdx.z;

    const int tx = tid & 31;
    const int ty = tid >> 5;
    const int wo = w0 + tx;
    const int ho = h0 + ty;
    const bool vout = (wo < 127) && (ho < 127);

    const float* xb = x + (size_t)b * (16 * 128 * 128);
    float acc = 0.0f;

    #pragma unroll 1
    for (int c = 0; c < 16; ++c) {
        const float* xc = xb + c * 16384;

        // ---- stage: per-element contributions for all 4 patch positions ----
        for (int e = tid; e < NELEM; e += 256) {
            int dy = e / HALO_W;
            int dx = e - dy * HALO_W;
            int h = h0 + dy, w = w0 + dx;
            float v = 0.0f;
            if (h < 128 && w < 128) v = __ldg(xc + h * 128 + w);

            // SiLU
            float ex = __expf(-v);
            float s  = __fdividef(v, 1.0f + ex);

            // spline interval + local coordinate
            float t  = (v - g0) * invh;
            int   i  = (int)floorf(t);
            i = min(max(i, 0), 10);
            float u  = t - (float)i;
            float m  = (v >= g0 && v < g11) ? 1.0f : 0.0f;

            const float4* cf = &sh_coef4[i * 4];
            float4 c0 = cf[0], c1 = cf[1], c2 = cf[2], c3 = cf[3];
            float sp0 = fmaf(fmaf(fmaf(c0.w, u, c0.z), u, c0.y), u, c0.x);
            float sp1 = fmaf(fmaf(fmaf(c1.w, u, c1.z), u, c1.y), u, c1.x);
            float sp2 = fmaf(fmaf(fmaf(c2.w, u, c2.z), u, c2.y), u, c2.x);
            float sp3 = fmaf(fmaf(fmaf(c3.w, u, c3.z), u, c3.y), u, c3.x);

            sh_d[0][e] = fmaf(bw0, s, sp0 * m);
            sh_d[1][e] = fmaf(bw1, s, sp1 * m);
            sh_d[2][e] = fmaf(bw2, s, sp2 * m);
            sh_d[3][e] = fmaf(bw3, s, sp3 * m);
        }
        __syncthreads();

        // ---- consume: output (ho,wo) uses element (ho+di, wo+dj) with k=di*2+dj
        if (vout) {
            int e0 = ty * HALO_W + tx;
            int e1 = e0 + HALO_W;
            acc += sh_d[0][e0] + sh_d[1][e0 + 1] + sh_d[2][e1] + sh_d[3][e1 + 1];
        }
        __syncthreads();
    }

    if (vout) {
        out[(size_t)b * (127 * 127) + ho * 127 + wo] = acc;
    }
}

extern "C" void kernel_launch(void* const* d_in, const int* in_sizes, int n_in,
                              void* d_out, int out_size)
{
    const float* x         = (const float*)d_in[0];
    const float* base_w    = (const float*)d_in[1];
    const float* spline_w  = (const float*)d_in[2];
    const float* spline_sc = (const float*)d_in[3];
    const float* grid      = (const float*)d_in[4];
    float* out = (float*)d_out;

    dim3 block(256);
    dim3 gridDim((127 + TW - 1) / TW,   // 4
                 (127 + TH - 1) / TH,   // 16
                 8);
    kan_conv_kernel<<<gridDim, block>>>(x, base_w, spline_w, spline_sc, grid, out);
}

// round 2
// speedup vs baseline: 1.2437x; 1.2437x over previous
#include <cuda_runtime.h>

// KAN conv2d: 2x2 unfold over (8,16,128,128), KANLinear(4->1), channel-sum
// -> (8,1,127,127) fp32.
//
// R2 design:
//  - Channel sum commutes with the 2x2 gather: accumulate D_k(h,w)=sum_c d_k
//    in REGISTERS across the 16-channel loop (no barriers inside), stage the
//    4 channel-summed planes in smem once, 1 syncthreads, gather, store.
//  - d_k(v) (= bw_k*silu(v) + spline_k(v)) tabulated by a tiny build kernel
//    into a 2049-node float4 LUT over [-4,4]; inner eval = 2x LDG.128 + lerp.
//    |v|>3.98 (prob ~0) falls back to exact base-only path (spline=0 there).

#define TW 32
#define TH 8
#define HALO_W 33
#define HALO_H 9
#define NELEM (HALO_W * HALO_H)   // 297
#define PLANE 304

#define LUT_N 2048
#define LUT_LO (-4.0f)
#define LUT_SCALE 256.0f          // 1/step, step = 8/2048

__device__ float4 g_lut[LUT_N + 1];

// ---------------------------------------------------------------------------
// Build kernel: exact closed-form d_k at each LUT node.
// ---------------------------------------------------------------------------
__global__ void build_lut_kernel(const float* __restrict__ base_w,
                                 const float* __restrict__ spline_w,
                                 const float* __restrict__ spline_sc,
                                 const float* __restrict__ grid)
{
    int j = blockIdx.x * blockDim.x + threadIdx.x;
    if (j > LUT_N) return;
    float v = LUT_LO + (float)j * (1.0f / LUT_SCALE);

    const float g0  = __ldg(grid);
    const float g1  = __ldg(grid + 1);
    const float g11 = __ldg(grid + 11);
    const float invh = 1.0f / (g1 - g0);

    // exact SiLU (same fast intrinsics as round-1 kernel, which verified at 5e-7)
    float ex = __expf(-v);
    float s  = __fdividef(v, 1.0f + ex);

    float sp[4] = {0.f, 0.f, 0.f, 0.f};
    if (v >= g0 && v < g11) {
        float t = (v - g0) * invh;
        int   i = min(max((int)floorf(t), 0), 10);
        float u = t - (float)i;
        float um = 1.0f - u;
        // basis values for j = i-3+m, m=0..3
        float b[4];
        b[0] = um * um * um * (1.0f / 6.0f);
        b[1] = ((3.0f * u - 6.0f) * u * u + 4.0f) * (1.0f / 6.0f);
        b[2] = (((-3.0f * u + 3.0f) * u + 3.0f) * u + 1.0f) * (1.0f / 6.0f);
        b[3] = u * u * u * (1.0f / 6.0f);
        #pragma unroll
        for (int m = 0; m < 4; ++m) {
            int jj = i + m - 3;
            if (jj >= 0 && jj < 8) {
                #pragma unroll
                for (int k = 0; k < 4; ++k)
                    sp[k] = fmaf(__ldg(spline_w + k * 8 + jj) * __ldg(spline_sc + k),
                                 b[m], sp[k]);
            }
        }
    }

    float4 r;
    r.x = fmaf(__ldg(base_w + 0), s, sp[0]);
    r.y = fmaf(__ldg(base_w + 1), s, sp[1]);
    r.z = fmaf(__ldg(base_w + 2), s, sp[2]);
    r.w = fmaf(__ldg(base_w + 3), s, sp[3]);
    g_lut[j] = r;
}

// ---------------------------------------------------------------------------
// Main kernel
// ---------------------------------------------------------------------------
__global__ __launch_bounds__(256)
void kan_conv_kernel(const float* __restrict__ x,
                     const float* __restrict__ base_w,
                     float* __restrict__ out)
{
    __shared__ float sh_d[4][PLANE];

    const int tid = threadIdx.x;
    const int w0 = blockIdx.x * TW;
    const int h0 = blockIdx.y * TH;
    const int b  = blockIdx.z;

    // element 1: e = tid (always < 297); element 2: e+256 (only tid < 41)
    const int e1 = tid;
    const int e2 = tid + 256;
    const bool has2 = (e2 < NELEM);

    int dy1 = e1 / HALO_W, dx1 = e1 - dy1 * HALO_W;
    int dy2 = e2 / HALO_W, dx2 = e2 - dy2 * HALO_W;
    // clamp: out-of-range halo elements are only consumed by invalid outputs
    int h1 = min(h0 + dy1, 127), w1 = min(w0 + dx1, 127);
    int h2 = min(h0 + dy2, 127), w2 = min(w0 + dx2, 127);
    const int off1 = h1 * 128 + w1;
    const int off2 = has2 ? (h2 * 128 + w2) : off1;

    const float bw0 = __ldg(base_w + 0);
    const float bw1 = __ldg(base_w + 1);
    const float bw2 = __ldg(base_w + 2);
    const float bw3 = __ldg(base_w + 3);

    const float* xb = x + (size_t)b * (16 * 128 * 128);

    float a0 = 0.f, a1 = 0.f, a2 = 0.f, a3 = 0.f;   // elem 1 accumulators
    float c0 = 0.f, c1 = 0.f, c2 = 0.f, c3 = 0.f;   // elem 2 accumulators

    #pragma unroll 4
    for (int c = 0; c < 16; ++c) {
        const float* xc = xb + c * 16384;
        float v1 = __ldg(xc + off1);
        float v2 = __ldg(xc + off2);

        // ---- elem 1 ----
        if (__builtin_expect(fabsf(v1) > 3.98f, 0)) {
            float s = __fdividef(v1, 1.0f + __expf(-v1));
            a0 = fmaf(bw0, s, a0); a1 = fmaf(bw1, s, a1);
            a2 = fmaf(bw2, s, a2); a3 = fmaf(bw3, s, a3);
        } else {
            float t = fmaf(v1, LUT_SCALE, -LUT_LO * LUT_SCALE);
            int   i = (int)t;
            float u = t - (float)i;
            float4 A = __ldg(&g_lut[i]);
            float4 B = __ldg(&g_lut[i + 1]);
            a0 += fmaf(u, B.x - A.x, A.x);
            a1 += fmaf(u, B.y - A.y, A.y);
            a2 += fmaf(u, B.z - A.z, A.z);
            a3 += fmaf(u, B.w - A.w, A.w);
        }

        // ---- elem 2 ----
        if (__builtin_expect(fabsf(v2) > 3.98f, 0)) {
            float s = __fdividef(v2, 1.0f + __expf(-v2));
            c0 = fmaf(bw0, s, c0); c1 = fmaf(bw1, s, c1);
            c2 = fmaf(bw2, s, c2); c3 = fmaf(bw3, s, c3);
        } else {
            float t = fmaf(v2, LUT_SCALE, -LUT_LO * LUT_SCALE);
            int   i = (int)t;
            float u = t - (float)i;
            float4 A = __ldg(&g_lut[i]);
            float4 B = __ldg(&g_lut[i + 1]);
            c0 += fmaf(u, B.x - A.x, A.x);
            c1 += fmaf(u, B.y - A.y, A.y);
            c2 += fmaf(u, B.z - A.z, A.z);
            c3 += fmaf(u, B.w - A.w, A.w);
        }
    }

    sh_d[0][e1] = a0; sh_d[1][e1] = a1; sh_d[2][e1] = a2; sh_d[3][e1] = a3;
    if (has2) {
        sh_d[0][e2] = c0; sh_d[1][e2] = c1; sh_d[2][e2] = c2; sh_d[3][e2] = c3;
    }
    __syncthreads();

    const int tx = tid & 31;
    const int ty = tid >> 5;
    const int wo = w0 + tx;
    const int ho = h0 + ty;
    if (wo < 127 && ho < 127) {
        int p0 = ty * HALO_W + tx;
        int p1 = p0 + HALO_W;
        float r = sh_d[0][p0] + sh_d[1][p0 + 1] + sh_d[2][p1] + sh_d[3][p1 + 1];
        out[(size_t)b * (127 * 127) + ho * 127 + wo] = r;
    }
}

// ---------------------------------------------------------------------------
extern "C" void kernel_launch(void* const* d_in, const int* in_sizes, int n_in,
                              void* d_out, int out_size)
{
    const float* x         = (const float*)d_in[0];
    const float* base_w    = (const float*)d_in[1];
    const float* spline_w  = (const float*)d_in[2];
    const float* spline_sc = (const float*)d_in[3];
    const float* grid      = (const float*)d_in[4];
    float* out = (float*)d_out;

    build_lut_kernel<<<(LUT_N + 1 + 255) / 256, 256>>>(base_w, spline_w, spline_sc, grid);

    dim3 block(256);
    dim3 gridDim((127 + TW - 1) / TW,   // 4
                 (127 + TH - 1) / TH,   // 16
                 8);
    kan_conv_kernel<<<gridDim, block>>>(x, base_w, out);
}